// round 1
// baseline (speedup 1.0000x reference)
#include <cuda_runtime.h>
#include <math.h>

#define N_TOKENS 8192
#define D_IN     1024
#define D_OUT    1024
#define N_EXP    8
#define ROUTER_BLOCKS 64

// ---------------- scratch (device globals: no allocation allowed) ----------------
__device__ int   g_e0[N_TOKENS], g_e1[N_TOKENS];
__device__ float g_w0[N_TOKENS], g_w1[N_TOKENS];
__device__ int   g_counts[N_EXP], g_offsets[N_EXP], g_cursor[N_EXP];
__device__ int   g_rows_token[2 * N_TOKENS];
__device__ float g_rows_w[2 * N_TOKENS];
__device__ float g_partial[ROUTER_BLOCKS * N_EXP];

// ---------------- zero counters (graph replays re-run everything) ----------------
__global__ void zero_kernel() {
    int t = threadIdx.x;
    if (t < N_EXP) { g_counts[t] = 0; g_cursor[t] = 0; }
}

// ---------------- router: logits, softmax, top-2, counts, aux partials ----------------
__global__ __launch_bounds__(256) void router_kernel(const float* __restrict__ x,
                                                     const float* __restrict__ Wr,
                                                     const float* __restrict__ br) {
    __shared__ float sWr[N_EXP * D_IN];   // 32 KB
    __shared__ float sSum[N_EXP];
    int tid = threadIdx.x;
    for (int i = tid; i < N_EXP * D_IN; i += 256) sWr[i] = Wr[i];
    if (tid < N_EXP) sSum[tid] = 0.f;
    __syncthreads();

    int warp = tid >> 5, lane = tid & 31;
    for (int t = 0; t < 16; ++t) {
        int n = blockIdx.x * 128 + warp * 16 + t;
        const float* xr = x + (size_t)n * D_IN;
        float acc[N_EXP];
        #pragma unroll
        for (int e = 0; e < N_EXP; ++e) acc[e] = 0.f;
        for (int i = lane; i < D_IN; i += 32) {
            float xi = xr[i];
            #pragma unroll
            for (int e = 0; e < N_EXP; ++e) acc[e] += xi * sWr[e * D_IN + i];
        }
        #pragma unroll
        for (int e = 0; e < N_EXP; ++e) {
            #pragma unroll
            for (int o = 16; o > 0; o >>= 1)
                acc[e] += __shfl_down_sync(0xffffffffu, acc[e], o);
        }
        if (lane == 0) {
            float logit[N_EXP], mx = -1e30f;
            #pragma unroll
            for (int e = 0; e < N_EXP; ++e) { logit[e] = acc[e] + br[e]; mx = fmaxf(mx, logit[e]); }
            float p[N_EXP], s = 0.f;
            #pragma unroll
            for (int e = 0; e < N_EXP; ++e) { p[e] = expf(logit[e] - mx); s += p[e]; }
            float inv = 1.f / s;
            #pragma unroll
            for (int e = 0; e < N_EXP; ++e) p[e] *= inv;
            // top-2 (strict > == lowest index wins on ties, matching jax top_k)
            int e0 = 0; float p0 = p[0];
            #pragma unroll
            for (int e = 1; e < N_EXP; ++e) if (p[e] > p0) { p0 = p[e]; e0 = e; }
            int e1 = -1; float p1 = -1e30f;
            #pragma unroll
            for (int e = 0; e < N_EXP; ++e) if (e != e0 && p[e] > p1) { p1 = p[e]; e1 = e; }
            float inv2 = 1.f / (p0 + p1);
            g_e0[n] = e0; g_e1[n] = e1;
            g_w0[n] = p0 * inv2; g_w1[n] = p1 * inv2;
            atomicAdd(&g_counts[e0], 1);
            atomicAdd(&g_counts[e1], 1);
            #pragma unroll
            for (int e = 0; e < N_EXP; ++e) atomicAdd(&sSum[e], p[e]);
        }
    }
    __syncthreads();
    if (tid < N_EXP) g_partial[blockIdx.x * N_EXP + tid] = sSum[tid];
}

// ---------------- offsets: 8-element exclusive scan ----------------
__global__ void offsets_kernel() {
    if (threadIdx.x == 0) {
        int s = 0;
        for (int e = 0; e < N_EXP; ++e) { g_offsets[e] = s; s += g_counts[e]; }
    }
}

// ---------------- scatter tokens into per-expert segments ----------------
__global__ void scatter_kernel() {
    int n = blockIdx.x * 256 + threadIdx.x;
    if (n >= N_TOKENS) return;
    int e0 = g_e0[n], e1 = g_e1[n];
    int p0 = atomicAdd(&g_cursor[e0], 1);
    int i0 = g_offsets[e0] + p0;
    g_rows_token[i0] = n; g_rows_w[i0] = g_w0[n];
    int p1 = atomicAdd(&g_cursor[e1], 1);
    int i1 = g_offsets[e1] + p1;
    g_rows_token[i1] = n; g_rows_w[i1] = g_w1[n];
}

// ---------------- out init: weighted bias combine ----------------
__global__ __launch_bounds__(256) void bias_kernel(const float* __restrict__ b,
                                                   float* __restrict__ out) {
    int n = blockIdx.x;
    int e0 = g_e0[n], e1 = g_e1[n];
    float w0 = g_w0[n], w1 = g_w1[n];
    const float4* b0 = (const float4*)(b + (size_t)e0 * D_OUT);
    const float4* b1 = (const float4*)(b + (size_t)e1 * D_OUT);
    float4* o = (float4*)(out + (size_t)n * D_OUT);
    int t = threadIdx.x;                 // 256 threads x float4 = 1024
    float4 x0 = b0[t], x1 = b1[t];
    float4 r;
    r.x = w0 * x0.x + w1 * x1.x;
    r.y = w0 * x0.y + w1 * x1.y;
    r.z = w0 * x0.z + w1 * x1.z;
    r.w = w0 * x0.w + w1 * x1.w;
    o[t] = r;
}

// ---------------- aux loss finalize (deterministic fixed-order reduction) ----------------
__global__ void aux_kernel(float* __restrict__ out_aux) {
    __shared__ float mp[N_EXP];
    int t = threadIdx.x;
    if (t < N_EXP) {
        float s = 0.f;
        for (int b = 0; b < ROUTER_BLOCKS; ++b) s += g_partial[b * N_EXP + t];
        mp[t] = s / (float)N_TOKENS;
    }
    __syncthreads();
    if (t == 0) {
        float a = 0.f;
        #pragma unroll
        for (int e = 0; e < N_EXP; ++e) { float d = mp[e] - 0.125f; a += d * d; }
        *out_aux = (a / (float)N_EXP) * 0.01f;
    }
}

// ---------------- gathered expert GEMM: out[tok] += w * (x[tok] @ W[e]) ----------------
#define BM 128
#define BN 128
#define BK 8

__global__ __launch_bounds__(256, 2) void gemm_kernel(const float* __restrict__ x,
                                                      const float* __restrict__ W,
                                                      float* __restrict__ out) {
    int e = blockIdx.z;
    int cnt = g_counts[e];
    int rowBase = blockIdx.x * BM;
    if (rowBase >= cnt) return;
    int off = g_offsets[e];
    int colBase = blockIdx.y * BN;
    const float* Wb = W + (size_t)e * D_IN * D_OUT;

    __shared__ float As[2][BK][BM];
    __shared__ float Bs[2][BK][BN];
    __shared__ int   sTok[BM];
    __shared__ float sW[BM];

    int tid = threadIdx.x;
    if (tid < BM) {
        int ti = rowBase + tid;
        if (ti < cnt) { sTok[tid] = g_rows_token[off + ti]; sW[tid] = g_rows_w[off + ti]; }
        else          { sTok[tid] = -1;                      sW[tid] = 0.f; }
    }
    __syncthreads();

    // A tile load mapping: 2 threads per row, float4 each (k-chunk of 8)
    int arow  = tid >> 1;
    int ahalf = (tid & 1) << 2;
    int tok   = sTok[arow];
    bool aval = (tok >= 0);
    const float* aPtr = x + (size_t)(aval ? tok : 0) * D_IN + ahalf;

    // B tile load mapping: thread -> (k row, 4 contiguous cols)
    int bk   = tid >> 5;
    int bcol = (tid & 31) << 2;
    const float* bPtr = Wb + (size_t)bk * D_OUT + colBase + bcol;

    int ty = tid >> 4, tx = tid & 15;
    float acc[8][8];
    #pragma unroll
    for (int i = 0; i < 8; ++i)
        #pragma unroll
        for (int j = 0; j < 8; ++j) acc[i][j] = 0.f;

    // preload tile 0
    float4 av = aval ? *(const float4*)(aPtr) : make_float4(0.f, 0.f, 0.f, 0.f);
    float4 bv = *(const float4*)(bPtr);
    As[0][ahalf + 0][arow] = av.x;
    As[0][ahalf + 1][arow] = av.y;
    As[0][ahalf + 2][arow] = av.z;
    As[0][ahalf + 3][arow] = av.w;
    *(float4*)&Bs[0][bk][bcol] = bv;
    __syncthreads();

    int buf = 0;
    for (int k0 = BK; k0 <= D_IN; k0 += BK) {
        bool more = (k0 < D_IN);
        if (more) {
            av = aval ? *(const float4*)(aPtr + k0) : make_float4(0.f, 0.f, 0.f, 0.f);
            bv = *(const float4*)(bPtr + (size_t)k0 * D_OUT);
        }
        #pragma unroll
        for (int k = 0; k < BK; ++k) {
            float a[8], b[8];
            *(float4*)&a[0] = *(const float4*)&As[buf][k][ty * 8];
            *(float4*)&a[4] = *(const float4*)&As[buf][k][ty * 8 + 4];
            *(float4*)&b[0] = *(const float4*)&Bs[buf][k][tx * 8];
            *(float4*)&b[4] = *(const float4*)&Bs[buf][k][tx * 8 + 4];
            #pragma unroll
            for (int i = 0; i < 8; ++i)
                #pragma unroll
                for (int j = 0; j < 8; ++j) acc[i][j] += a[i] * b[j];
        }
        if (more) {
            As[buf ^ 1][ahalf + 0][arow] = av.x;
            As[buf ^ 1][ahalf + 1][arow] = av.y;
            As[buf ^ 1][ahalf + 2][arow] = av.z;
            As[buf ^ 1][ahalf + 3][arow] = av.w;
            *(float4*)&Bs[buf ^ 1][bk][bcol] = bv;
            __syncthreads();
            buf ^= 1;
        }
    }

    // epilogue: out[token] += w * acc  (2 commutative adds per element onto exact init)
    #pragma unroll
    for (int i = 0; i < 8; ++i) {
        int r = ty * 8 + i;
        int t = sTok[r];
        if (t < 0) continue;
        float w = sW[r];
        float* orow = out + (size_t)t * D_OUT + colBase + tx * 8;
        #pragma unroll
        for (int j = 0; j < 8; ++j) atomicAdd(&orow[j], w * acc[i][j]);
    }
}

// ---------------- launch ----------------
extern "C" void kernel_launch(void* const* d_in, const int* in_sizes, int n_in,
                              void* d_out, int out_size) {
    const float* x  = (const float*)d_in[0];
    const float* W  = (const float*)d_in[1];
    const float* b  = (const float*)d_in[2];
    const float* Wr = (const float*)d_in[3];
    const float* br = (const float*)d_in[4];
    float* out = (float*)d_out;

    zero_kernel<<<1, 32>>>();
    router_kernel<<<ROUTER_BLOCKS, 256>>>(x, Wr, br);
    offsets_kernel<<<1, 32>>>();
    scatter_kernel<<<(N_TOKENS + 255) / 256, 256>>>();
    bias_kernel<<<N_TOKENS, 256>>>(b, out);
    if (out_size > N_TOKENS * D_OUT)
        aux_kernel<<<1, 32>>>(out + (size_t)N_TOKENS * D_OUT);

    dim3 grid((N_TOKENS + BM - 1) / BM, D_OUT / BN, N_EXP);
    gemm_kernel<<<grid, 256>>>(x, W, out);
}

// round 4
// speedup vs baseline: 2.0492x; 2.0492x over previous
#include <cuda_runtime.h>
#include <cuda_bf16.h>
#include <math.h>

#define N_TOKENS 8192
#define D_IN     1024
#define D_OUT    1024
#define N_EXP    8
#define ROUTER_BLOCKS 64

// ---------------- scratch (device globals: no allocation allowed) ----------------
__device__ int   g_e0[N_TOKENS], g_e1[N_TOKENS];
__device__ float g_w0[N_TOKENS], g_w1[N_TOKENS];
__device__ int   g_pos0[N_TOKENS], g_pos1[N_TOKENS];
__device__ int   g_counts[N_EXP], g_offsets[N_EXP], g_cursor[N_EXP];
__device__ int   g_rows_token[2 * N_TOKENS];
__device__ float g_partial[ROUTER_BLOCKS * N_EXP];

// bf16 split buffers: x (hi/lo) and W transposed (hi/lo)
__device__ __nv_bfloat16 g_xhi[N_TOKENS * D_IN];
__device__ __nv_bfloat16 g_xlo[N_TOKENS * D_IN];
__device__ __nv_bfloat16 g_wthi[N_EXP * D_IN * D_OUT];   // [e][n][k]
__device__ __nv_bfloat16 g_wtlo[N_EXP * D_IN * D_OUT];

// per-assignment raw expert outputs (unweighted, no bias)
__device__ float g_scr[2 * N_TOKENS * D_OUT];            // 64 MB

// ---------------- PTX helpers ----------------
__device__ __forceinline__ unsigned smem_u32(const void* p) {
    unsigned a;
    asm("{ .reg .u64 t; cvta.to.shared.u64 t, %1; cvt.u32.u64 %0, t; }" : "=r"(a) : "l"(p));
    return a;
}
#define CP_ASYNC16(dst, src) \
    asm volatile("cp.async.cg.shared.global [%0], [%1], 16;" :: "r"(dst), "l"(src))
#define CP_COMMIT() asm volatile("cp.async.commit_group;" ::: "memory")
#define CP_WAIT(n)  asm volatile("cp.async.wait_group %0;" :: "n"(n) : "memory")

#define LDSM4(r0, r1, r2, r3, addr) \
    asm volatile("ldmatrix.sync.aligned.m8n8.x4.shared.b16 {%0,%1,%2,%3}, [%4];" \
                 : "=r"(r0), "=r"(r1), "=r"(r2), "=r"(r3) : "r"(addr))

#define MMA16816(d, a0, a1, a2, a3, b0, b1) \
    asm volatile("mma.sync.aligned.m16n8k16.row.col.f32.bf16.bf16.f32 " \
                 "{%0,%1,%2,%3}, {%4,%5,%6,%7}, {%8,%9}, {%0,%1,%2,%3};" \
                 : "+f"((d)[0]), "+f"((d)[1]), "+f"((d)[2]), "+f"((d)[3]) \
                 : "r"(a0), "r"(a1), "r"(a2), "r"(a3), "r"(b0), "r"(b1))

#define SWZ(o) ((unsigned)(o) ^ (((unsigned)(o) >> 3) & 0x70u))

// ---------------- zero counters ----------------
__global__ void zero_kernel() {
    int t = threadIdx.x;
    if (t < N_EXP) { g_counts[t] = 0; g_cursor[t] = 0; }
}

// ---------------- split-convert x -> bf16 hi/lo ----------------
__global__ __launch_bounds__(256) void cvt_x_kernel(const float* __restrict__ x) {
    int idx4 = blockIdx.x * 256 + threadIdx.x;
    const float4* xv = (const float4*)x;
    float4 v = xv[idx4];
    float f[4] = {v.x, v.y, v.z, v.w};
    unsigned short h[4], l[4];
    #pragma unroll
    for (int i = 0; i < 4; ++i) {
        __nv_bfloat16 hb = __float2bfloat16_rn(f[i]);
        float r = f[i] - __bfloat162float(hb);
        __nv_bfloat16 lb = __float2bfloat16_rn(r);
        h[i] = __bfloat16_as_ushort(hb);
        l[i] = __bfloat16_as_ushort(lb);
    }
    uint2 hp, lp;
    hp.x = (unsigned)h[0] | ((unsigned)h[1] << 16);
    hp.y = (unsigned)h[2] | ((unsigned)h[3] << 16);
    lp.x = (unsigned)l[0] | ((unsigned)l[1] << 16);
    lp.y = (unsigned)l[2] | ((unsigned)l[3] << 16);
    ((uint2*)g_xhi)[idx4] = hp;
    ((uint2*)g_xlo)[idx4] = lp;
}

// ---------------- transpose + split-convert W[e][k][n] -> Wt[e][n][k] ----------------
__global__ __launch_bounds__(256) void cvt_w_kernel(const float* __restrict__ W) {
    __shared__ float tile[32][33];
    int e = blockIdx.z;
    int kt = blockIdx.x * 32, nt = blockIdx.y * 32;
    int tx = threadIdx.x, ty = threadIdx.y;   // block (32,8)
    const float* Wb = W + (size_t)e * D_IN * D_OUT;
    #pragma unroll
    for (int j = 0; j < 4; ++j)
        tile[ty + j * 8][tx] = Wb[(size_t)(kt + ty + j * 8) * D_OUT + nt + tx];
    __syncthreads();
    #pragma unroll
    for (int j = 0; j < 4; ++j) {
        int n = nt + ty + j * 8;
        float v = tile[tx][ty + j * 8];
        __nv_bfloat16 hb = __float2bfloat16_rn(v);
        float r = v - __bfloat162float(hb);
        __nv_bfloat16 lb = __float2bfloat16_rn(r);
        size_t o = ((size_t)e * D_OUT + n) * D_IN + kt + tx;
        g_wthi[o] = hb;
        g_wtlo[o] = lb;
    }
}

// ---------------- router ----------------
__global__ __launch_bounds__(256) void router_kernel(const float* __restrict__ x,
                                                     const float* __restrict__ Wr,
                                                     const float* __restrict__ br) {
    __shared__ float sWr[N_EXP * D_IN];
    __shared__ float sSum[N_EXP];
    int tid = threadIdx.x;
    for (int i = tid; i < N_EXP * D_IN; i += 256) sWr[i] = Wr[i];
    if (tid < N_EXP) sSum[tid] = 0.f;
    __syncthreads();

    int warp = tid >> 5, lane = tid & 31;
    for (int t = 0; t < 16; ++t) {
        int n = blockIdx.x * 128 + warp * 16 + t;
        const float* xr = x + (size_t)n * D_IN;
        float acc[N_EXP];
        #pragma unroll
        for (int e = 0; e < N_EXP; ++e) acc[e] = 0.f;
        for (int i = lane; i < D_IN; i += 32) {
            float xi = xr[i];
            #pragma unroll
            for (int e = 0; e < N_EXP; ++e) acc[e] += xi * sWr[e * D_IN + i];
        }
        #pragma unroll
        for (int e = 0; e < N_EXP; ++e) {
            #pragma unroll
            for (int o = 16; o > 0; o >>= 1)
                acc[e] += __shfl_down_sync(0xffffffffu, acc[e], o);
        }
        if (lane == 0) {
            float logit[N_EXP], mx = -1e30f;
            #pragma unroll
            for (int e = 0; e < N_EXP; ++e) { logit[e] = acc[e] + br[e]; mx = fmaxf(mx, logit[e]); }
            float p[N_EXP], s = 0.f;
            #pragma unroll
            for (int e = 0; e < N_EXP; ++e) { p[e] = expf(logit[e] - mx); s += p[e]; }
            float inv = 1.f / s;
            #pragma unroll
            for (int e = 0; e < N_EXP; ++e) p[e] *= inv;
            int e0 = 0; float p0 = p[0];
            #pragma unroll
            for (int e = 1; e < N_EXP; ++e) if (p[e] > p0) { p0 = p[e]; e0 = e; }
            int e1 = -1; float p1 = -1e30f;
            #pragma unroll
            for (int e = 0; e < N_EXP; ++e) if (e != e0 && p[e] > p1) { p1 = p[e]; e1 = e; }
            float inv2 = 1.f / (p0 + p1);
            g_e0[n] = e0; g_e1[n] = e1;
            g_w0[n] = p0 * inv2; g_w1[n] = p1 * inv2;
            atomicAdd(&g_counts[e0], 1);
            atomicAdd(&g_counts[e1], 1);
            #pragma unroll
            for (int e = 0; e < N_EXP; ++e) atomicAdd(&sSum[e], p[e]);
        }
    }
    __syncthreads();
    if (tid < N_EXP) g_partial[blockIdx.x * N_EXP + tid] = sSum[tid];
}

// ---------------- offsets ----------------
__global__ void offsets_kernel() {
    if (threadIdx.x == 0) {
        int s = 0;
        for (int e = 0; e < N_EXP; ++e) { g_offsets[e] = s; s += g_counts[e]; }
    }
}

// ---------------- scatter (also records per-token row positions) ----------------
__global__ void scatter_kernel() {
    int n = blockIdx.x * 256 + threadIdx.x;
    if (n >= N_TOKENS) return;
    int e0 = g_e0[n], e1 = g_e1[n];
    int i0 = g_offsets[e0] + atomicAdd(&g_cursor[e0], 1);
    g_rows_token[i0] = n;
    g_pos0[n] = i0;
    int i1 = g_offsets[e1] + atomicAdd(&g_cursor[e1], 1);
    g_rows_token[i1] = n;
    g_pos1[n] = i1;
}

// ---------------- aux loss ----------------
__global__ void aux_kernel(float* __restrict__ out_aux) {
    __shared__ float mp[N_EXP];
    int t = threadIdx.x;
    if (t < N_EXP) {
        float s = 0.f;
        for (int b = 0; b < ROUTER_BLOCKS; ++b) s += g_partial[b * N_EXP + t];
        mp[t] = s / (float)N_TOKENS;
    }
    __syncthreads();
    if (t == 0) {
        float a = 0.f;
        #pragma unroll
        for (int e = 0; e < N_EXP; ++e) { float d = mp[e] - 0.125f; a += d * d; }
        *out_aux = (a / (float)N_EXP) * 0.01f;
    }
}

// ---------------- mma.sync bf16x3 gathered GEMM ----------------
// BM=128 rows x BN=256 cols, 512 threads (16 warps: 2 x 8, warp tile 64x32)
// K chunks of 64 bf16; 48 chunks = 3 split terms x 1024.
// SMEM (dynamic, 96 KB): [A0|B0][A1|B1], SW128 swizzled, 128B rows.
// Per chunk: A = 128x128B = 1024 16B xfers (2/thread), B = 256x128B = 2048 (4/thread).
#define BM 128
#define BN 256
#define NCH 48
#define A_BYTES 16384
#define B_BYTES 32768
#define BUF_STRIDE (A_BYTES + B_BYTES)
#define SM_TOTAL (2 * BUF_STRIDE)

struct ChunkSrc {
    const __nv_bfloat16* A;
    const __nv_bfloat16* B;   // expert/nBase adjusted, [n][k], k-stride 1, n-stride D_IN
    int ksrc;
};

__device__ __forceinline__ ChunkSrc chunk_src(int c, int e, int nBase) {
    ChunkSrc s;
    int term = c >> 4;               // 0: hi*hi, 1: hi*lo, 2: lo*hi
    s.ksrc = (c & 15) << 6;
    s.A = (term == 2) ? g_xlo : g_xhi;
    const __nv_bfloat16* Bsrc = (term == 1) ? g_wtlo : g_wthi;
    s.B = Bsrc + ((size_t)e * D_OUT + nBase) * D_IN;
    return s;
}

__global__ __launch_bounds__(512) void gemm_mma_kernel() {
    extern __shared__ char smem[];
    int e = blockIdx.z;
    int cnt = g_counts[e];
    int rowBase = blockIdx.x * BM;
    if (rowBase >= cnt) return;
    int off = g_offsets[e];
    int nBase = blockIdx.y * BN;

    __shared__ int sTok[BM];
    int tid = threadIdx.x, wid = tid >> 5, lane = tid & 31;
    if (tid < BM) {
        int ti = rowBase + tid;
        sTok[tid] = (ti < cnt) ? g_rows_token[off + ti] : 0;
    }
    __syncthreads();

    unsigned sb = smem_u32(smem);
    int warpM = wid >> 3, warpN = wid & 7;

    float acc[4][4][4];
    #pragma unroll
    for (int i = 0; i < 4; ++i)
        #pragma unroll
        for (int j = 0; j < 4; ++j)
            #pragma unroll
            for (int k = 0; k < 4; ++k) acc[i][j][k] = 0.f;

    // A load mapping: 2 transfers/thread; q = i*512+tid, row = q>>3 (0..127), seg = q&7
    int aRow0 = tid >> 3, aSeg0 = tid & 7;
    int aRow1 = (512 + tid) >> 3, aSeg1 = tid & 7;   // row + 64
    unsigned aOff0 = SWZ(aRow0 * 128 + aSeg0 * 16);
    unsigned aOff1 = SWZ(aRow1 * 128 + aSeg1 * 16);
    int aTok0 = sTok[aRow0];
    int aTok1 = sTok[aRow1];

    // ---- preload chunk 0 ----
    {
        ChunkSrc s = chunk_src(0, e, nBase);
        CP_ASYNC16(sb + aOff0, s.A + (size_t)aTok0 * D_IN + s.ksrc + aSeg0 * 8);
        CP_ASYNC16(sb + aOff1, s.A + (size_t)aTok1 * D_IN + s.ksrc + aSeg1 * 8);
        #pragma unroll
        for (int i = 0; i < 4; ++i) {
            int q = i * 512 + tid;
            int row = q >> 3, seg = q & 7;
            CP_ASYNC16(sb + A_BYTES + SWZ(row * 128 + seg * 16),
                       s.B + (size_t)row * D_IN + s.ksrc + seg * 8);
        }
        CP_COMMIT();
    }

    for (int c = 0; c < NCH; ++c) {
        int buf = c & 1;
        if (c + 1 < NCH) {
            ChunkSrc s = chunk_src(c + 1, e, nBase);
            unsigned base = sb + (buf ^ 1) * BUF_STRIDE;
            CP_ASYNC16(base + aOff0, s.A + (size_t)aTok0 * D_IN + s.ksrc + aSeg0 * 8);
            CP_ASYNC16(base + aOff1, s.A + (size_t)aTok1 * D_IN + s.ksrc + aSeg1 * 8);
            #pragma unroll
            for (int i = 0; i < 4; ++i) {
                int q = i * 512 + tid;
                int row = q >> 3, seg = q & 7;
                CP_ASYNC16(base + A_BYTES + SWZ(row * 128 + seg * 16),
                           s.B + (size_t)row * D_IN + s.ksrc + seg * 8);
            }
            CP_COMMIT();
            CP_WAIT(1);
        } else {
            CP_WAIT(0);
        }
        __syncthreads();

        unsigned aBase = sb + buf * BUF_STRIDE;
        unsigned bBase = aBase + A_BYTES;
        #pragma unroll
        for (int ks = 0; ks < 4; ++ks) {
            unsigned ar[4][4], br[2][4];
            unsigned colOff = ks * 32 + ((lane >> 4) << 4);
            #pragma unroll
            for (int mt = 0; mt < 4; ++mt) {
                int row = warpM * 64 + mt * 16 + (lane & 15);
                unsigned addr = aBase + SWZ(row * 128 + colOff);
                LDSM4(ar[mt][0], ar[mt][1], ar[mt][2], ar[mt][3], addr);
            }
            #pragma unroll
            for (int nt = 0; nt < 2; ++nt) {
                int row = warpN * 32 + nt * 16 + (lane & 15);
                unsigned addr = bBase + SWZ(row * 128 + colOff);
                LDSM4(br[nt][0], br[nt][1], br[nt][2], br[nt][3], addr);
            }
            #pragma unroll
            for (int mt = 0; mt < 4; ++mt) {
                #pragma unroll
                for (int nt = 0; nt < 2; ++nt) {
                    MMA16816(acc[mt][nt * 2 + 0], ar[mt][0], ar[mt][1], ar[mt][2], ar[mt][3],
                             br[nt][0], br[nt][2]);
                    MMA16816(acc[mt][nt * 2 + 1], ar[mt][0], ar[mt][1], ar[mt][2], ar[mt][3],
                             br[nt][1], br[nt][3]);
                }
            }
        }
        __syncthreads();
    }

    // epilogue: raw (unweighted) rows -> scratch, guarded by segment count
    #pragma unroll
    for (int mt = 0; mt < 4; ++mt) {
        int r0 = warpM * 64 + mt * 16 + (lane >> 2);
        #pragma unroll
        for (int nj = 0; nj < 4; ++nj) {
            int col = nBase + warpN * 32 + nj * 8 + (lane & 3) * 2;
            int ti = rowBase + r0;
            if (ti < cnt) {
                float2 v = make_float2(acc[mt][nj][0], acc[mt][nj][1]);
                *(float2*)&g_scr[(size_t)(off + ti) * D_OUT + col] = v;
            }
            int ti2 = ti + 8;
            if (ti2 < cnt) {
                float2 v = make_float2(acc[mt][nj][2], acc[mt][nj][3]);
                *(float2*)&g_scr[(size_t)(off + ti2) * D_OUT + col] = v;
            }
        }
    }
}

// ---------------- combine: out = w0*(y0 + b[e0]) + w1*(y1 + b[e1]) ----------------
__global__ __launch_bounds__(256) void combine_kernel(const float* __restrict__ b,
                                                      float* __restrict__ out) {
    int n = blockIdx.x;
    int e0 = g_e0[n], e1 = g_e1[n];
    float w0 = g_w0[n], w1 = g_w1[n];
    int i0 = g_pos0[n], i1 = g_pos1[n];
    const float4* y0 = (const float4*)(g_scr + (size_t)i0 * D_OUT);
    const float4* y1 = (const float4*)(g_scr + (size_t)i1 * D_OUT);
    const float4* b0 = (const float4*)(b + (size_t)e0 * D_OUT);
    const float4* b1 = (const float4*)(b + (size_t)e1 * D_OUT);
    float4* o = (float4*)(out + (size_t)n * D_OUT);
    int t = threadIdx.x;
    float4 a0 = y0[t], a1 = y1[t], c0 = b0[t], c1 = b1[t];
    float4 r;
    r.x = w0 * (a0.x + c0.x) + w1 * (a1.x + c1.x);
    r.y = w0 * (a0.y + c0.y) + w1 * (a1.y + c1.y);
    r.z = w0 * (a0.z + c0.z) + w1 * (a1.z + c1.z);
    r.w = w0 * (a0.w + c0.w) + w1 * (a1.w + c1.w);
    o[t] = r;
}

// ---------------- launch ----------------
extern "C" void kernel_launch(void* const* d_in, const int* in_sizes, int n_in,
                              void* d_out, int out_size) {
    const float* x  = (const float*)d_in[0];
    const float* W  = (const float*)d_in[1];
    const float* b  = (const float*)d_in[2];
    const float* Wr = (const float*)d_in[3];
    const float* br = (const float*)d_in[4];
    float* out = (float*)d_out;

    cudaFuncSetAttribute(gemm_mma_kernel, cudaFuncAttributeMaxDynamicSharedMemorySize, SM_TOTAL);

    zero_kernel<<<1, 32>>>();
    cvt_x_kernel<<<N_TOKENS * D_IN / 1024, 256>>>(x);
    {
        dim3 g(D_IN / 32, D_OUT / 32, N_EXP);
        cvt_w_kernel<<<g, dim3(32, 8)>>>(W);
    }
    router_kernel<<<ROUTER_BLOCKS, 256>>>(x, Wr, br);
    offsets_kernel<<<1, 32>>>();
    scatter_kernel<<<(N_TOKENS + 255) / 256, 256>>>();

    dim3 grid(2 * N_TOKENS / BM, D_OUT / BN, N_EXP);
    gemm_mma_kernel<<<grid, 512, SM_TOTAL>>>();

    combine_kernel<<<N_TOKENS, 256>>>(b, out);
    if (out_size > N_TOKENS * D_OUT)
        aux_kernel<<<1, 32>>>(out + (size_t)N_TOKENS * D_OUT);
}

// round 5
// speedup vs baseline: 2.4155x; 1.1787x over previous
#include <cuda_runtime.h>
#include <cuda_bf16.h>
#include <math.h>

#define N_TOKENS 8192
#define D_IN     1024
#define D_OUT    1024
#define N_EXP    8
#define ROUTER_BLOCKS 256

// ---------------- scratch (device globals: no allocation allowed) ----------------
__device__ int   g_e0[N_TOKENS], g_e1[N_TOKENS];
__device__ float g_w0[N_TOKENS], g_w1[N_TOKENS];
__device__ int   g_pos0[N_TOKENS], g_pos1[N_TOKENS];
__device__ int   g_counts[N_EXP], g_offsets[N_EXP], g_cursor[N_EXP];
__device__ int   g_rows_token[2 * N_TOKENS];
__device__ float g_partial[ROUTER_BLOCKS * N_EXP];

// bf16 split buffers: x (hi/lo) and W transposed (hi/lo)
__device__ __nv_bfloat16 g_xhi[N_TOKENS * D_IN];
__device__ __nv_bfloat16 g_xlo[N_TOKENS * D_IN];
__device__ __nv_bfloat16 g_wthi[N_EXP * D_IN * D_OUT];   // [e][n][k]
__device__ __nv_bfloat16 g_wtlo[N_EXP * D_IN * D_OUT];

// per-assignment raw expert outputs (unweighted, no bias)
__device__ float g_scr[2 * N_TOKENS * D_OUT];            // 64 MB

// ---------------- PTX helpers ----------------
__device__ __forceinline__ unsigned smem_u32(const void* p) {
    unsigned a;
    asm("{ .reg .u64 t; cvta.to.shared.u64 t, %1; cvt.u32.u64 %0, t; }" : "=r"(a) : "l"(p));
    return a;
}
#define CP_ASYNC16(dst, src) \
    asm volatile("cp.async.cg.shared.global [%0], [%1], 16;" :: "r"(dst), "l"(src))
#define CP_COMMIT() asm volatile("cp.async.commit_group;" ::: "memory")
#define CP_WAIT(n)  asm volatile("cp.async.wait_group %0;" :: "n"(n) : "memory")

#define LDSM4(r0, r1, r2, r3, addr) \
    asm volatile("ldmatrix.sync.aligned.m8n8.x4.shared.b16 {%0,%1,%2,%3}, [%4];" \
                 : "=r"(r0), "=r"(r1), "=r"(r2), "=r"(r3) : "r"(addr))

#define MMA16816(d, a0, a1, a2, a3, b0, b1) \
    asm volatile("mma.sync.aligned.m16n8k16.row.col.f32.bf16.bf16.f32 " \
                 "{%0,%1,%2,%3}, {%4,%5,%6,%7}, {%8,%9}, {%0,%1,%2,%3};" \
                 : "+f"((d)[0]), "+f"((d)[1]), "+f"((d)[2]), "+f"((d)[3]) \
                 : "r"(a0), "r"(a1), "r"(a2), "r"(a3), "r"(b0), "r"(b1))

#define SWZ(o) ((unsigned)(o) ^ (((unsigned)(o) >> 3) & 0x70u))

// ---------------- zero counters ----------------
__global__ void zero_kernel() {
    int t = threadIdx.x;
    if (t < N_EXP) { g_counts[t] = 0; g_cursor[t] = 0; }
}

// ---------------- split-convert x -> bf16 hi/lo ----------------
__global__ __launch_bounds__(256) void cvt_x_kernel(const float* __restrict__ x) {
    int idx4 = blockIdx.x * 256 + threadIdx.x;
    const float4* xv = (const float4*)x;
    float4 v = xv[idx4];
    float f[4] = {v.x, v.y, v.z, v.w};
    unsigned short h[4], l[4];
    #pragma unroll
    for (int i = 0; i < 4; ++i) {
        __nv_bfloat16 hb = __float2bfloat16_rn(f[i]);
        float r = f[i] - __bfloat162float(hb);
        __nv_bfloat16 lb = __float2bfloat16_rn(r);
        h[i] = __bfloat16_as_ushort(hb);
        l[i] = __bfloat16_as_ushort(lb);
    }
    uint2 hp, lp;
    hp.x = (unsigned)h[0] | ((unsigned)h[1] << 16);
    hp.y = (unsigned)h[2] | ((unsigned)h[3] << 16);
    lp.x = (unsigned)l[0] | ((unsigned)l[1] << 16);
    lp.y = (unsigned)l[2] | ((unsigned)l[3] << 16);
    ((uint2*)g_xhi)[idx4] = hp;
    ((uint2*)g_xlo)[idx4] = lp;
}

// ---------------- transpose + split-convert W[e][k][n] -> Wt[e][n][k] ----------------
__global__ __launch_bounds__(256) void cvt_w_kernel(const float* __restrict__ W) {
    __shared__ float tile[32][33];
    int e = blockIdx.z;
    int kt = blockIdx.x * 32, nt = blockIdx.y * 32;
    int tx = threadIdx.x, ty = threadIdx.y;   // block (32,8)
    const float* Wb = W + (size_t)e * D_IN * D_OUT;
    #pragma unroll
    for (int j = 0; j < 4; ++j)
        tile[ty + j * 8][tx] = Wb[(size_t)(kt + ty + j * 8) * D_OUT + nt + tx];
    __syncthreads();
    #pragma unroll
    for (int j = 0; j < 4; ++j) {
        int n = nt + ty + j * 8;
        float v = tile[tx][ty + j * 8];
        __nv_bfloat16 hb = __float2bfloat16_rn(v);
        float r = v - __bfloat162float(hb);
        __nv_bfloat16 lb = __float2bfloat16_rn(r);
        size_t o = ((size_t)e * D_OUT + n) * D_IN + kt + tx;
        g_wthi[o] = hb;
        g_wtlo[o] = lb;
    }
}

// ---------------- router: 256 blocks x 8 warps x 4 tokens ----------------
__global__ __launch_bounds__(256) void router_kernel(const float* __restrict__ x,
                                                     const float* __restrict__ Wr,
                                                     const float* __restrict__ br) {
    __shared__ float sWr[N_EXP * D_IN];
    __shared__ float sSum[N_EXP];
    int tid = threadIdx.x;
    for (int i = tid; i < N_EXP * D_IN; i += 256) sWr[i] = Wr[i];
    if (tid < N_EXP) sSum[tid] = 0.f;
    __syncthreads();

    int warp = tid >> 5, lane = tid & 31;
    const float4* sWr4 = (const float4*)sWr;
    for (int t = 0; t < 4; ++t) {
        int n = blockIdx.x * 32 + warp * 4 + t;
        const float4* xr4 = (const float4*)(x + (size_t)n * D_IN);
        float acc[N_EXP];
        #pragma unroll
        for (int e = 0; e < N_EXP; ++e) acc[e] = 0.f;
        #pragma unroll
        for (int i = 0; i < 8; ++i) {
            float4 xv = xr4[lane + i * 32];
            #pragma unroll
            for (int e = 0; e < N_EXP; ++e) {
                float4 wv = sWr4[e * 256 + lane + i * 32];
                acc[e] += xv.x * wv.x + xv.y * wv.y + xv.z * wv.z + xv.w * wv.w;
            }
        }
        #pragma unroll
        for (int e = 0; e < N_EXP; ++e) {
            #pragma unroll
            for (int o = 16; o > 0; o >>= 1)
                acc[e] += __shfl_down_sync(0xffffffffu, acc[e], o);
        }
        if (lane == 0) {
            float logit[N_EXP], mx = -1e30f;
            #pragma unroll
            for (int e = 0; e < N_EXP; ++e) { logit[e] = acc[e] + br[e]; mx = fmaxf(mx, logit[e]); }
            float p[N_EXP], s = 0.f;
            #pragma unroll
            for (int e = 0; e < N_EXP; ++e) { p[e] = expf(logit[e] - mx); s += p[e]; }
            float inv = 1.f / s;
            #pragma unroll
            for (int e = 0; e < N_EXP; ++e) p[e] *= inv;
            int e0 = 0; float p0 = p[0];
            #pragma unroll
            for (int e = 1; e < N_EXP; ++e) if (p[e] > p0) { p0 = p[e]; e0 = e; }
            int e1 = -1; float p1 = -1e30f;
            #pragma unroll
            for (int e = 0; e < N_EXP; ++e) if (e != e0 && p[e] > p1) { p1 = p[e]; e1 = e; }
            float inv2 = 1.f / (p0 + p1);
            g_e0[n] = e0; g_e1[n] = e1;
            g_w0[n] = p0 * inv2; g_w1[n] = p1 * inv2;
            atomicAdd(&g_counts[e0], 1);
            atomicAdd(&g_counts[e1], 1);
            #pragma unroll
            for (int e = 0; e < N_EXP; ++e) atomicAdd(&sSum[e], p[e]);
        }
    }
    __syncthreads();
    if (tid < N_EXP) g_partial[blockIdx.x * N_EXP + tid] = sSum[tid];
}

// ---------------- offsets ----------------
__global__ void offsets_kernel() {
    if (threadIdx.x == 0) {
        int s = 0;
        for (int e = 0; e < N_EXP; ++e) { g_offsets[e] = s; s += g_counts[e]; }
    }
}

// ---------------- scatter (also records per-token row positions) ----------------
__global__ void scatter_kernel() {
    int n = blockIdx.x * 256 + threadIdx.x;
    if (n >= N_TOKENS) return;
    int e0 = g_e0[n], e1 = g_e1[n];
    int i0 = g_offsets[e0] + atomicAdd(&g_cursor[e0], 1);
    g_rows_token[i0] = n;
    g_pos0[n] = i0;
    int i1 = g_offsets[e1] + atomicAdd(&g_cursor[e1], 1);
    g_rows_token[i1] = n;
    g_pos1[n] = i1;
}

// ---------------- aux loss ----------------
__global__ void aux_kernel(float* __restrict__ out_aux) {
    __shared__ float mp[N_EXP];
    int t = threadIdx.x;
    if (t < N_EXP) {
        float s = 0.f;
        for (int b = 0; b < ROUTER_BLOCKS; ++b) s += g_partial[b * N_EXP + t];
        mp[t] = s / (float)N_TOKENS;
    }
    __syncthreads();
    if (t == 0) {
        float a = 0.f;
        #pragma unroll
        for (int e = 0; e < N_EXP; ++e) { float d = mp[e] - 0.125f; a += d * d; }
        *out_aux = (a / (float)N_EXP) * 0.01f;
    }
}

// ---------------- mma.sync bf16x3 gathered GEMM ----------------
// BM=128 x BN=128, 256 threads (8 warps: 2M x 4N, warp tile 64x32).
// K chunks of 64 bf16; 48 chunks = 3 split terms x 1024.
// 3-stage cp.async pipeline; stage = A(16KB) + B(16KB) = 32 KB; 96 KB total.
// Per chunk per tile: 128 rows x 8 segs = 1024 16B xfers each for A and B (4/thread each).
#define BM 128
#define BN 128
#define NCH 48
#define NSTAGE 3
#define A_BYTES 16384
#define B_BYTES 16384
#define BUF_STRIDE (A_BYTES + B_BYTES)
#define SM_TOTAL (NSTAGE * BUF_STRIDE)

struct ChunkSrc {
    const __nv_bfloat16* A;
    const __nv_bfloat16* B;   // expert/nBase adjusted, [n][k], k-stride 1, n-stride D_IN
    int ksrc;
};

__device__ __forceinline__ ChunkSrc chunk_src(int c, int e, int nBase) {
    ChunkSrc s;
    int term = c >> 4;               // 0: hi*hi, 1: hi*lo, 2: lo*hi
    s.ksrc = (c & 15) << 6;
    s.A = (term == 2) ? g_xlo : g_xhi;
    const __nv_bfloat16* Bsrc = (term == 1) ? g_wtlo : g_wthi;
    s.B = Bsrc + ((size_t)e * D_OUT + nBase) * D_IN;
    return s;
}

__global__ __launch_bounds__(256) void gemm_mma_kernel() {
    extern __shared__ char smem[];
    int e = blockIdx.z;
    int cnt = g_counts[e];
    int rowBase = blockIdx.x * BM;
    if (rowBase >= cnt) return;
    int off = g_offsets[e];
    int nBase = blockIdx.y * BN;

    __shared__ int sTok[BM];
    int tid = threadIdx.x, wid = tid >> 5, lane = tid & 31;
    if (tid < BM) {
        int ti = rowBase + tid;
        sTok[tid] = (ti < cnt) ? g_rows_token[off + ti] : 0;
    }
    __syncthreads();

    unsigned sb = smem_u32(smem);
    int warpM = wid >> 2, warpN = wid & 3;

    float acc[4][4][4];
    #pragma unroll
    for (int i = 0; i < 4; ++i)
        #pragma unroll
        for (int j = 0; j < 4; ++j)
            #pragma unroll
            for (int k = 0; k < 4; ++k) acc[i][j][k] = 0.f;

    // load mapping: 4 xfers/thread each for A and B; q = i*256+tid, row = q>>3, seg = q&7
    int ldRow = tid >> 3, ldSeg = tid & 7;
    unsigned ldOff[4];
    int aTok[4];
    #pragma unroll
    for (int i = 0; i < 4; ++i) {
        int row = ldRow + i * 32;
        ldOff[i] = SWZ(row * 128 + ldSeg * 16);
        aTok[i] = sTok[row];
    }

    // ---- prologue: stages 0..NSTAGE-2 ----
    #pragma unroll
    for (int s = 0; s < NSTAGE - 1; ++s) {
        ChunkSrc cs = chunk_src(s, e, nBase);
        unsigned base = sb + s * BUF_STRIDE;
        #pragma unroll
        for (int i = 0; i < 4; ++i) {
            CP_ASYNC16(base + ldOff[i],
                       cs.A + (size_t)aTok[i] * D_IN + cs.ksrc + ldSeg * 8);
            CP_ASYNC16(base + A_BYTES + ldOff[i],
                       cs.B + (size_t)(ldRow + i * 32) * D_IN + cs.ksrc + ldSeg * 8);
        }
        CP_COMMIT();
    }

    for (int c = 0; c < NCH; ++c) {
        int buf = c % NSTAGE;
        CP_WAIT(NSTAGE - 2);
        __syncthreads();

        // issue load for chunk c + NSTAGE - 1 into the buffer consumed at iter c-1
        if (c + NSTAGE - 1 < NCH) {
            ChunkSrc cs = chunk_src(c + NSTAGE - 1, e, nBase);
            unsigned base = sb + ((c + NSTAGE - 1) % NSTAGE) * BUF_STRIDE;
            #pragma unroll
            for (int i = 0; i < 4; ++i) {
                CP_ASYNC16(base + ldOff[i],
                           cs.A + (size_t)aTok[i] * D_IN + cs.ksrc + ldSeg * 8);
                CP_ASYNC16(base + A_BYTES + ldOff[i],
                           cs.B + (size_t)(ldRow + i * 32) * D_IN + cs.ksrc + ldSeg * 8);
            }
            CP_COMMIT();
        }

        unsigned aBase = sb + buf * BUF_STRIDE;
        unsigned bBase = aBase + A_BYTES;
        #pragma unroll
        for (int ks = 0; ks < 4; ++ks) {
            unsigned ar[4][4], br[2][4];
            unsigned colOff = ks * 32 + ((lane >> 4) << 4);
            #pragma unroll
            for (int mt = 0; mt < 4; ++mt) {
                int row = warpM * 64 + mt * 16 + (lane & 15);
                unsigned addr = aBase + SWZ(row * 128 + colOff);
                LDSM4(ar[mt][0], ar[mt][1], ar[mt][2], ar[mt][3], addr);
            }
            #pragma unroll
            for (int nt = 0; nt < 2; ++nt) {
                int row = warpN * 32 + nt * 16 + (lane & 15);
                unsigned addr = bBase + SWZ(row * 128 + colOff);
                LDSM4(br[nt][0], br[nt][1], br[nt][2], br[nt][3], addr);
            }
            #pragma unroll
            for (int mt = 0; mt < 4; ++mt) {
                #pragma unroll
                for (int nt = 0; nt < 2; ++nt) {
                    MMA16816(acc[mt][nt * 2 + 0], ar[mt][0], ar[mt][1], ar[mt][2], ar[mt][3],
                             br[nt][0], br[nt][2]);
                    MMA16816(acc[mt][nt * 2 + 1], ar[mt][0], ar[mt][1], ar[mt][2], ar[mt][3],
                             br[nt][1], br[nt][3]);
                }
            }
        }
        __syncthreads();
    }

    // epilogue: raw (unweighted) rows -> scratch, guarded by segment count
    #pragma unroll
    for (int mt = 0; mt < 4; ++mt) {
        int r0 = warpM * 64 + mt * 16 + (lane >> 2);
        #pragma unroll
        for (int nj = 0; nj < 4; ++nj) {
            int col = nBase + warpN * 32 + nj * 8 + (lane & 3) * 2;
            int ti = rowBase + r0;
            if (ti < cnt) {
                float2 v = make_float2(acc[mt][nj][0], acc[mt][nj][1]);
                *(float2*)&g_scr[(size_t)(off + ti) * D_OUT + col] = v;
            }
            int ti2 = ti + 8;
            if (ti2 < cnt) {
                float2 v = make_float2(acc[mt][nj][2], acc[mt][nj][3]);
                *(float2*)&g_scr[(size_t)(off + ti2) * D_OUT + col] = v;
            }
        }
    }
}

// ---------------- combine: out = w0*(y0 + b[e0]) + w1*(y1 + b[e1]) ----------------
__global__ __launch_bounds__(256) void combine_kernel(const float* __restrict__ b,
                                                      float* __restrict__ out) {
    int n = blockIdx.x;
    int e0 = g_e0[n], e1 = g_e1[n];
    float w0 = g_w0[n], w1 = g_w1[n];
    int i0 = g_pos0[n], i1 = g_pos1[n];
    const float4* y0 = (const float4*)(g_scr + (size_t)i0 * D_OUT);
    const float4* y1 = (const float4*)(g_scr + (size_t)i1 * D_OUT);
    const float4* b0 = (const float4*)(b + (size_t)e0 * D_OUT);
    const float4* b1 = (const float4*)(b + (size_t)e1 * D_OUT);
    float4* o = (float4*)(out + (size_t)n * D_OUT);
    int t = threadIdx.x;
    float4 a0 = y0[t], a1 = y1[t], c0 = b0[t], c1 = b1[t];
    float4 r;
    r.x = w0 * (a0.x + c0.x) + w1 * (a1.x + c1.x);
    r.y = w0 * (a0.y + c0.y) + w1 * (a1.y + c1.y);
    r.z = w0 * (a0.z + c0.z) + w1 * (a1.z + c1.z);
    r.w = w0 * (a0.w + c0.w) + w1 * (a1.w + c1.w);
    o[t] = r;
}

// ---------------- launch ----------------
extern "C" void kernel_launch(void* const* d_in, const int* in_sizes, int n_in,
                              void* d_out, int out_size) {
    const float* x  = (const float*)d_in[0];
    const float* W  = (const float*)d_in[1];
    const float* b  = (const float*)d_in[2];
    const float* Wr = (const float*)d_in[3];
    const float* br = (const float*)d_in[4];
    float* out = (float*)d_out;

    cudaFuncSetAttribute(gemm_mma_kernel, cudaFuncAttributeMaxDynamicSharedMemorySize, SM_TOTAL);

    zero_kernel<<<1, 32>>>();
    cvt_x_kernel<<<N_TOKENS * D_IN / 1024, 256>>>(x);
    {
        dim3 g(D_IN / 32, D_OUT / 32, N_EXP);
        cvt_w_kernel<<<g, dim3(32, 8)>>>(W);
    }
    router_kernel<<<ROUTER_BLOCKS, 256>>>(x, Wr, br);
    offsets_kernel<<<1, 32>>>();
    scatter_kernel<<<(N_TOKENS + 255) / 256, 256>>>();

    dim3 grid(2 * N_TOKENS / BM, D_OUT / BN, N_EXP);
    gemm_mma_kernel<<<grid, 256, SM_TOTAL>>>();

    combine_kernel<<<N_TOKENS, 256>>>(b, out);
    if (out_size > N_TOKENS * D_OUT)
        aux_kernel<<<1, 32>>>(out + (size_t)N_TOKENS * D_OUT);
}